// round 8
// baseline (speedup 1.0000x reference)
#include <cuda_runtime.h>
#include <cuda_bf16.h>

#define NUM_CLASSES 1024
#define FEAT_DIM    512
#define BATCH       16384
#define ALPHA       0.5f
#define MAXC        192   // cap on tracked samples/class (Binomial mean 16, sd 4; max ~40)

// Scratch (allocation-free rule): zero-init at module load; cl_main re-zeros
// g_cnt in its epilogue so every graph replay sees zeros.
__device__ int g_cnt[NUM_CLASSES];
__device__ int g_slot[NUM_CLASSES * MAXC];

// Kernel 1: histogram + scatter sample indices into per-class slots.
__global__ __launch_bounds__(256) void cl_hist_scatter(const int* __restrict__ labels) {
    int i = blockIdx.x * blockDim.x + threadIdx.x;
    if (i < BATCH) {
        int c = labels[i];
        int p = atomicAdd(&g_cnt[c], 1);
        if (p < MAXC) g_slot[c * MAXC + p] = i;
    }
}

// Kernel 2: ONE WARP PER CLASS (grid 1024, block 32). No barriers, no smem.
// Lane covers 16 floats of the 512-float row (4 strided float4 loads).
// 2-deep register pipeline (fA/fB) keeps 8 independent LDG.128 in flight.
// Slot indices are loaded one 32-batch at a time and broadcast via shuffle.
// delta accumulates in lane registers; newc row is written directly.
__global__ __launch_bounds__(32, 16) void cl_main(
    const float4* __restrict__ feat,     // [BATCH][128] float4
    const float4* __restrict__ centers,  // [C][128] float4
    float*        __restrict__ result,   // [BATCH]
    float4*       __restrict__ newc)     // [C][128] float4
{
    const int c    = blockIdx.x;
    const int lane = threadIdx.x;

    const int cnt = g_cnt[c];
    const int n   = cnt < MAXC ? cnt : MAXC;

    const int*    slot = g_slot + c * MAXC;
    const float4* crow = centers + c * 128;

    // First batch of sample indices: lane m holds sample m (m < 32).
    int myidx = 0;
    if (lane < n) myidx = slot[lane];

    // Prefetch samples 0 and 1 before the center row (overlap latencies).
    float4 fA[4], fB[4];
    int bA = 0, bB = 0;
    if (n > 0) {
        bA = __shfl_sync(0xffffffffu, myidx, 0);
        const float4* fr = feat + (size_t)bA * 128;
        #pragma unroll
        for (int q = 0; q < 4; q++) fA[q] = fr[lane + 32 * q];
    }
    if (n > 1) {
        bB = __shfl_sync(0xffffffffu, myidx, 1);
        const float4* fr = feat + (size_t)bB * 128;
        #pragma unroll
        for (int q = 0; q < 4; q++) fB[q] = fr[lane + 32 * q];
    }

    float4 ctr[4];
    #pragma unroll
    for (int k = 0; k < 4; k++) ctr[k] = crow[lane + 32 * k];

    float4 dl[4];
    #pragma unroll
    for (int k = 0; k < 4; k++) dl[k] = make_float4(0.f, 0.f, 0.f, 0.f);

    // Process sample j from register set F, then prefetch sample j+2 into F.
    #define CL_STEP(F, BV, J)                                                  \
    do {                                                                       \
        float ss = 0.f;                                                        \
        _Pragma("unroll")                                                      \
        for (int q = 0; q < 4; q++) {                                          \
            float4 d;                                                          \
            d.x = ctr[q].x - F[q].x;                                           \
            d.y = ctr[q].y - F[q].y;                                           \
            d.z = ctr[q].z - F[q].z;                                           \
            d.w = ctr[q].w - F[q].w;                                           \
            dl[q].x += d.x; dl[q].y += d.y;                                    \
            dl[q].z += d.z; dl[q].w += d.w;                                    \
            ss += d.x * d.x + d.y * d.y + d.z * d.z + d.w * d.w;               \
        }                                                                      \
        const int b_out = BV;                                                  \
        const int jn = (J) + 2;                                                \
        if (jn < n) {                                                          \
            if ((jn & 31) == 0) myidx = slot[jn + lane];                       \
            BV = __shfl_sync(0xffffffffu, myidx, jn & 31);                     \
            const float4* fr = feat + (size_t)BV * 128;                        \
            _Pragma("unroll")                                                  \
            for (int q = 0; q < 4; q++) F[q] = fr[lane + 32 * q];              \
        }                                                                      \
        _Pragma("unroll")                                                      \
        for (int o = 16; o; o >>= 1)                                           \
            ss += __shfl_xor_sync(0xffffffffu, ss, o);                         \
        if (lane == 0) result[b_out] = ss;                                     \
    } while (0)

    int m = 0;
    while (m < n) {
        CL_STEP(fA, bA, m);
        m++;
        if (m >= n) break;
        CL_STEP(fB, bB, m);
        m++;
    }
    #undef CL_STEP

    // Write the new center row: lane covers float4s lane, lane+32, +64, +96.
    const float s = ALPHA / (float)(cnt + 1);
    #pragma unroll
    for (int k = 0; k < 4; k++) {
        float4 nc;
        nc.x = ctr[k].x - dl[k].x * s;
        nc.y = ctr[k].y - dl[k].y * s;
        nc.z = ctr[k].z - dl[k].z * s;
        nc.w = ctr[k].w - dl[k].w * s;
        newc[c * 128 + lane + 32 * k] = nc;
    }

    if (lane == 0) g_cnt[c] = 0;   // leave scratch zeroed for the next replay
}

extern "C" void kernel_launch(void* const* d_in, const int* in_sizes, int n_in,
                              void* d_out, int out_size) {
    const float* features = (const float*)d_in[0];   // 16384*512
    const float* centers  = (const float*)d_in[1];   // 1024*512
    const int*   labels   = (const int*)  d_in[2];   // 16384

    float* out        = (float*)d_out;
    float* result     = out;            // [16384]
    float* newcenters = out + BATCH;    // [1024*512], 64KB offset -> 16B aligned

    cl_hist_scatter<<<BATCH / 256, 256>>>(labels);

    cl_main<<<NUM_CLASSES, 32>>>(
        (const float4*)features,
        (const float4*)centers,
        result,
        (float4*)newcenters);
}